// round 11
// baseline (speedup 1.0000x reference)
#include <cuda_runtime.h>
#include <cuda_bf16.h>
#include <cuda_fp16.h>
#include <cstdint>

#define N_NODES 50000
#define N_EDGES 800000
#define D 128
#define SCAN_BLK 1024
#define NBLK ((N_NODES + SCAN_BLK - 1) / SCAN_BLK)   // 49
#define MTILE 128
#define NTILES ((N_NODES + MTILE - 1) / MTILE)       // 391

// ---------------- device scratch ----------------
__device__ int   g_deg[N_NODES];
__device__ int   g_rowoff[N_NODES + 1];
__device__ unsigned short g_rank[N_EDGES];           // edge rank within dst bucket
__device__ int   g_edgesrc[N_EDGES];
__device__ int   g_bsum[NBLK];
__device__ int   g_bpre[NBLK];
__device__ int   g_scan_ctr = 0;
__device__ float g_hneigh[(size_t)N_NODES * D];      // fp32 mean-aggregated feats
__device__ unsigned short g_feat16[(size_t)N_NODES * D];  // fp16 copy of feat (gather side)
__device__ unsigned short g_Whi[128 * 256];          // [n][k]: k<128 Wself, k>=128 Wneigh
__device__ unsigned short g_Wlo[128 * 256];
__device__ float g_bcat[D];
__device__ int   g_is64;

// ---------------- small helpers ----------------
__device__ __forceinline__ int edge_idx(const void* p, int i, int is64) {
    return is64 ? (int)((const long long*)p)[i] : ((const int*)p)[i];
}
__device__ __forceinline__ void bf_split(float x, unsigned short& hi, unsigned short& lo) {
    __nv_bfloat16 h = __float2bfloat16_rn(x);
    hi = ((__nv_bfloat16_raw)h).x;
    float r = x - __bfloat162float(h);
    __nv_bfloat16 l = __float2bfloat16_rn(r);
    lo = ((__nv_bfloat16_raw)l).x;
}
__device__ __forceinline__ uint32_t smem_u32(const void* p) {
    uint32_t a;
    asm("{ .reg .u64 t; cvta.to.shared.u64 t, %1; cvt.u32.u64 %0, t; }" : "=r"(a) : "l"(p));
    return a;
}
// warp-level MMA primitives (sm_80 PTX — safe for the harness's sm_103 ptxas target)
__device__ __forceinline__ void ldsm4(uint32_t* r, uint32_t addr) {
    asm volatile("ldmatrix.sync.aligned.m8n8.x4.shared.b16 {%0,%1,%2,%3}, [%4];"
        : "=r"(r[0]), "=r"(r[1]), "=r"(r[2]), "=r"(r[3]) : "r"(addr));
}
__device__ __forceinline__ void mma16816(float* d, const uint32_t* a, const uint32_t* b) {
    asm volatile(
        "mma.sync.aligned.m16n8k16.row.col.f32.bf16.bf16.f32 "
        "{%0,%1,%2,%3}, {%4,%5,%6,%7}, {%8,%9}, {%0,%1,%2,%3};"
        : "+f"(d[0]), "+f"(d[1]), "+f"(d[2]), "+f"(d[3])
        : "r"(a[0]), "r"(a[1]), "r"(a[2]), "r"(a[3]), "r"(b[0]), "r"(b[1]));
}

// ---------------- prep: detect dtype, zero deg, split W, fused bias --------
__global__ void k_prep(const float* __restrict__ Wself, const float* __restrict__ bself,
                       const float* __restrict__ Wneigh, const float* __restrict__ bias,
                       const unsigned* __restrict__ src_raw) {
    int i = blockIdx.x * blockDim.x + threadIdx.x;
    if (blockIdx.x == 0) {                       // int64-vs-int32 detection
        __shared__ unsigned sor[8];
        int t = threadIdx.x, lane = t & 31, w = t >> 5;
        unsigned v = src_raw[2 * t + 1];
        #pragma unroll
        for (int off = 16; off > 0; off >>= 1) v |= __shfl_xor_sync(0xffffffffu, v, off);
        if (lane == 0) sor[w] = v;
        __syncthreads();
        if (t == 0) {
            unsigned o = 0;
            #pragma unroll
            for (int j = 0; j < 8; j++) o |= sor[j];
            g_is64 = (o == 0) ? 1 : 0;
            g_rowoff[N_NODES] = N_EDGES;
            g_scan_ctr = 0;
        }
    }
    if (i < N_NODES) g_deg[i] = 0;
    if (i < 128 * 256) {
        int n = i >> 8, k = i & 255;
        float w = (k < 128) ? Wself[n * 128 + k] : Wneigh[n * 128 + (k - 128)];
        unsigned short hi, lo;
        bf_split(w, hi, lo);
        g_Whi[i] = hi; g_Wlo[i] = lo;
    }
    if (i < D) g_bcat[i] = bself[i] + bias[i];
}

// ---------------- hist + feat->fp16 conversion (fused, 800k threads) -------
// Atomic-latency work (hist) and bandwidth work (convert) overlap in one
// kernel. atomicAdd return value = this edge's rank within its dst bucket.
__global__ void k_hist_conv(const void* __restrict__ dst,
                            const float* __restrict__ feat) {
    int e = blockIdx.x * blockDim.x + threadIdx.x;
    if (e >= N_EDGES) return;
    // convert 8 floats (800k threads x 8 = 6.4M = N_NODES*D exactly)
    {
        float4 a = __ldcs(&((const float4*)feat)[2 * e]);
        float4 b = __ldcs(&((const float4*)feat)[2 * e + 1]);
        __half2 h0 = __float22half2_rn(make_float2(a.x, a.y));
        __half2 h1 = __float22half2_rn(make_float2(a.z, a.w));
        __half2 h2 = __float22half2_rn(make_float2(b.x, b.y));
        __half2 h3 = __float22half2_rn(make_float2(b.z, b.w));
        uint4 o;
        o.x = *(uint32_t*)&h0; o.y = *(uint32_t*)&h1;
        o.z = *(uint32_t*)&h2; o.w = *(uint32_t*)&h3;
        ((uint4*)g_feat16)[e] = o;
    }
    int d = edge_idx(dst, e, g_is64);
    unsigned short rk = (unsigned short)atomicAdd(&g_deg[d], 1);
    __stcs(&g_rank[e], rk);
}

// block-level exclusive scan + last-block scans the 49 partials
__global__ void k_scan1() {
    __shared__ int wsum[32];
    __shared__ int s_last;
    int t = threadIdx.x, lane = t & 31, w = t >> 5;
    int i = blockIdx.x * SCAN_BLK + t;
    int v = (i < N_NODES) ? g_deg[i] : 0;
    int x = v;
    #pragma unroll
    for (int off = 1; off < 32; off <<= 1) {
        int y = __shfl_up_sync(0xffffffff, x, off);
        if (lane >= off) x += y;
    }
    if (lane == 31) wsum[w] = x;
    __syncthreads();
    if (w == 0) {
        int s = wsum[lane];
        #pragma unroll
        for (int off = 1; off < 32; off <<= 1) {
            int y = __shfl_up_sync(0xffffffff, s, off);
            if (lane >= off) s += y;
        }
        wsum[lane] = s;
    }
    __syncthreads();
    int pre = (w > 0) ? wsum[w - 1] : 0;
    if (i < N_NODES) g_rowoff[i] = x + pre - v;       // block-local exclusive
    if (t == SCAN_BLK - 1) g_bsum[blockIdx.x] = x + pre;
    if (t == 0) {
        __threadfence();
        s_last = (atomicAdd(&g_scan_ctr, 1) == NBLK - 1) ? 1 : 0;
    }
    __syncthreads();
    if (s_last) {
        __shared__ int ws2[2];
        if (t < 64) {
            int v2 = (t < NBLK) ? g_bsum[t] : 0;
            int x2 = v2;
            #pragma unroll
            for (int off = 1; off < 32; off <<= 1) {
                int y = __shfl_up_sync(0xffffffff, x2, off);
                if (lane >= off) x2 += y;
            }
            if (lane == 31) ws2[w] = x2;
            __syncthreads();
            if (w == 1) x2 += ws2[0];
            if (t < NBLK) g_bpre[t] = x2 - v2;
        } else {
            __syncthreads();
        }
        if (t == 0) g_scan_ctr = 0;                   // reset for next replay
    }
}

// scatter: atomic-free, rank precomputed in hist
__global__ void k_scatter(const void* __restrict__ src, const void* __restrict__ dst) {
    int e = blockIdx.x * blockDim.x + threadIdx.x;
    if (e < N_EDGES) {
        int is64 = g_is64;
        int d = edge_idx(dst, e, is64);
        int s = edge_idx(src, e, is64);
        int rk = (int)__ldcs(&g_rank[e]);
        __stcs(&g_edgesrc[g_rowoff[d] + g_bpre[d >> 10] + rk], s);
    }
}

// ---------------- SpMM: warp per node, fp16 gather + fp32 mean -------------
__global__ void k_spmm() {
    int g = (blockIdx.x * blockDim.x + threadIdx.x) >> 5;
    int lane = threadIdx.x & 31;
    if (g >= N_NODES) return;
    int beg = g_rowoff[g] + g_bpre[g >> 10];
    int end = (g == N_NODES - 1) ? N_EDGES : g_rowoff[g + 1] + g_bpre[(g + 1) >> 10];
    float4 acc = make_float4(0.f, 0.f, 0.f, 0.f);
    int e = beg;
    for (; e + 7 < end; e += 8) {                    // 8 outstanding LDG.64/lane
        uint2 f[8];
        #pragma unroll
        for (int j = 0; j < 8; j++) {
            int s = __ldcs(&g_edgesrc[e + j]);
            f[j] = *(const uint2*)(g_feat16 + (size_t)s * D + lane * 4);
        }
        #pragma unroll
        for (int j = 0; j < 8; j++) {
            float2 a = __half22float2(*(__half2*)&f[j].x);
            float2 b = __half22float2(*(__half2*)&f[j].y);
            acc.x += a.x; acc.y += a.y; acc.z += b.x; acc.w += b.y;
        }
    }
    for (; e < end; e++) {
        int s = g_edgesrc[e];
        uint2 fv = *(const uint2*)(g_feat16 + (size_t)s * D + lane * 4);
        float2 a = __half22float2(*(__half2*)&fv.x);
        float2 b = __half22float2(*(__half2*)&fv.y);
        acc.x += a.x; acc.y += a.y; acc.z += b.x; acc.w += b.y;
    }
    float inv = (end > beg) ? 1.0f / (float)(end - beg) : 0.0f;
    acc.x *= inv; acc.y *= inv; acc.z *= inv; acc.w *= inv;
    *(float4*)(g_hneigh + (size_t)g * D + lane * 4) = acc;
}

// ---------------- HMMA bf16x3 GEMM: out = [feat|hneigh] @ W^T + bcat --------
// Block 256 thr / 8 warps. Tile 128 rows x 128 cols, K=256 in 4 phases of 64.
// A staged from fp32 (feat: phases 0-1, hneigh: phases 2-3) with inline
// hi/lo bf16 split. smem: Ahi/Alo/Bhi/Blo @ 128 x 72 bf16 -> 72KB total.
// Split product: D += Ahi*Bhi + Ahi*Blo + Alo*Bhi  (fp32 accum).
#define AS 72
#define GSMEM (4 * 128 * AS * 2)
__global__ void __launch_bounds__(256, 2) k_gemm_mma(const float* __restrict__ feat,
                                                     float* __restrict__ out) {
    extern __shared__ unsigned short sm[];
    unsigned short* sAhi = sm;
    unsigned short* sAlo = sm + 128 * AS;
    unsigned short* sBhi = sm + 2 * 128 * AS;
    unsigned short* sBlo = sm + 3 * 128 * AS;
    int tid = threadIdx.x, l = tid & 31, wid = tid >> 5;
    int wm = wid >> 1, wn = wid & 1;
    int row0 = blockIdx.x * MTILE;

    float acc[2][8][4] = {};

    uint32_t sbase = smem_u32(sm);
    uint32_t aRow = (uint32_t)(wm * 32 + (l & 7) + ((l >> 3) & 1) * 8);
    uint32_t aK   = (uint32_t)((l >> 4) * 8);
    uint32_t aHi  = sbase + (aRow * AS + aK) * 2;
    uint32_t aLo  = aHi + 128 * AS * 2;
    uint32_t bRow = (uint32_t)(wn * 64 + (l & 7) + (l >> 4) * 8);
    uint32_t bK   = (uint32_t)(((l >> 3) & 1) * 8);
    uint32_t bHi  = sbase + 2 * 128 * AS * 2 + (bRow * AS + bK) * 2;
    uint32_t bLo  = bHi + 128 * AS * 2;

    #pragma unroll 1
    for (int ph = 0; ph < 4; ph++) {
        int kb = ph * 64;
        const float* srcA = (ph < 2) ? (feat + ph * 64)
                                     : (g_hneigh + (ph - 2) * 64);
        // stage A: 128 rows x 64 k fp32 -> split into hi/lo bf16
        for (int i = tid; i < 2048; i += 256) {       // float4 units
            int r = i >> 4, c = i & 15;
            int grow = row0 + r;
            float4 f = make_float4(0.f, 0.f, 0.f, 0.f);
            if (grow < N_NODES)
                f = *(const float4*)(srcA + (size_t)grow * D + c * 4);
            ushort4 h, lo4;
            bf_split(f.x, h.x, lo4.x); bf_split(f.y, h.y, lo4.y);
            bf_split(f.z, h.z, lo4.z); bf_split(f.w, h.w, lo4.w);
            *(ushort4*)(sAhi + r * AS + c * 4) = h;
            *(ushort4*)(sAlo + r * AS + c * 4) = lo4;
        }
        // stage B: 128 rows x 64 k bf16 hi/lo
        for (int i = tid; i < 1024; i += 256) {       // uint4 units (8 bf16)
            int r = i >> 3, c = i & 7;
            *(uint4*)(sBhi + r * AS + c * 8) =
                *(const uint4*)(g_Whi + (size_t)r * 256 + kb + c * 8);
            *(uint4*)(sBlo + r * AS + c * 8) =
                *(const uint4*)(g_Wlo + (size_t)r * 256 + kb + c * 8);
        }
        __syncthreads();
        #pragma unroll
        for (int ks = 0; ks < 4; ks++) {
            uint32_t ah[2][4], al[2][4];
            ldsm4(ah[0], aHi + ks * 32);
            ldsm4(ah[1], aHi + ks * 32 + 16 * AS * 2);
            ldsm4(al[0], aLo + ks * 32);
            ldsm4(al[1], aLo + ks * 32 + 16 * AS * 2);
            #pragma unroll
            for (int np = 0; np < 4; np++) {
                uint32_t bh[4], bl[4];
                ldsm4(bh, bHi + ks * 32 + np * 16 * AS * 2);
                ldsm4(bl, bLo + ks * 32 + np * 16 * AS * 2);
                #pragma unroll
                for (int mt = 0; mt < 2; mt++) {
                    mma16816(acc[mt][2 * np + 0], ah[mt], bh + 0);
                    mma16816(acc[mt][2 * np + 0], ah[mt], bl + 0);
                    mma16816(acc[mt][2 * np + 0], al[mt], bh + 0);
                    mma16816(acc[mt][2 * np + 1], ah[mt], bh + 2);
                    mma16816(acc[mt][2 * np + 1], ah[mt], bl + 2);
                    mma16816(acc[mt][2 * np + 1], al[mt], bh + 2);
                }
            }
        }
        __syncthreads();
    }

    // epilogue: c-frag lane l -> rows l/4 (+8), cols 2*(l%4) (+1)
    #pragma unroll
    for (int mt = 0; mt < 2; mt++) {
        #pragma unroll
        for (int half = 0; half < 2; half++) {
            int row = row0 + wm * 32 + mt * 16 + (l >> 2) + half * 8;
            if (row >= N_NODES) continue;
            #pragma unroll
            for (int nt = 0; nt < 8; nt++) {
                int col = wn * 64 + nt * 8 + (l & 3) * 2;
                float2 b = *(const float2*)(g_bcat + col);
                float2 o;
                o.x = acc[mt][nt][2 * half + 0] + b.x;
                o.y = acc[mt][nt][2 * half + 1] + b.y;
                *(float2*)(out + (size_t)row * D + col) = o;
            }
        }
    }
}

// ---------------- launcher ----------------
extern "C" void kernel_launch(void* const* d_in, const int* in_sizes, int n_in,
                              void* d_out, int out_size) {
    const float* feat   = (const float*)d_in[0];
    const void*  src    = d_in[1];
    const void*  dst    = d_in[2];
    const float* Wself  = (const float*)d_in[3];
    const float* bself  = (const float*)d_in[4];
    const float* Wneigh = (const float*)d_in[5];
    const float* bias   = (const float*)d_in[6];
    float* out = (float*)d_out;

    cudaFuncSetAttribute(k_gemm_mma, cudaFuncAttributeMaxDynamicSharedMemorySize, GSMEM);

    k_prep<<<(N_NODES + 255) / 256, 256>>>(Wself, bself, Wneigh, bias,
                                           (const unsigned*)src);
    k_hist_conv<<<(N_EDGES + 255) / 256, 256>>>(dst, feat);
    k_scan1<<<NBLK, SCAN_BLK>>>();
    k_scatter<<<(N_EDGES + 255) / 256, 256>>>(src, dst);
    k_spmm<<<(N_NODES * 32 + 255) / 256, 256>>>();
    k_gemm_mma<<<NTILES, 256, GSMEM>>>(feat, out);
}

// round 13
// speedup vs baseline: 1.0586x; 1.0586x over previous
#include <cuda_runtime.h>
#include <cuda_bf16.h>
#include <cuda_fp16.h>
#include <cstdint>

#define N_NODES 50000
#define N_EDGES 800000
#define D 128
#define SCAN_BLK 1024
#define NBLK ((N_NODES + SCAN_BLK - 1) / SCAN_BLK)   // 49
#define MTILE 128
#define NTILES ((N_NODES + MTILE - 1) / MTILE)       // 391

// ---------------- device scratch ----------------
__device__ int   g_deg[N_NODES];
__device__ int   g_rowoff[N_NODES + 1];
__device__ unsigned short g_rank[N_EDGES];           // edge rank within dst bucket
__device__ unsigned short g_edgesrc[N_EDGES];        // node ids < 65536 -> ushort
__device__ int   g_bsum[NBLK];
__device__ int   g_bpre[NBLK];
__device__ int   g_scan_ctr = 0;
__device__ float g_hneigh[(size_t)N_NODES * D];      // fp32 mean-aggregated feats
__device__ unsigned short g_feat16[(size_t)N_NODES * D];  // fp16 feat (gather side)
__device__ unsigned short g_Wh16[128 * 256];         // fp16 W: [n][k] k<128 Wself, else Wneigh
__device__ float g_bcat[D];
__device__ int   g_is64;

// ---------------- small helpers ----------------
__device__ __forceinline__ int edge_idx(const void* p, int i, int is64) {
    return is64 ? (int)((const long long*)p)[i] : ((const int*)p)[i];
}
__device__ __forceinline__ void h_split(float x, unsigned short& hi, unsigned short& lo) {
    __half h = __float2half_rn(x);
    hi = *(unsigned short*)&h;
    float r = x - __half2float(h);
    __half l = __float2half_rn(r);
    lo = *(unsigned short*)&l;
}
__device__ __forceinline__ uint32_t smem_u32(const void* p) {
    uint32_t a;
    asm("{ .reg .u64 t; cvta.to.shared.u64 t, %1; cvt.u32.u64 %0, t; }" : "=r"(a) : "l"(p));
    return a;
}
// warp-level MMA primitives (sm_80 PTX — safe for the harness's sm_103 ptxas target)
__device__ __forceinline__ void ldsm4(uint32_t* r, uint32_t addr) {
    asm volatile("ldmatrix.sync.aligned.m8n8.x4.shared.b16 {%0,%1,%2,%3}, [%4];"
        : "=r"(r[0]), "=r"(r[1]), "=r"(r[2]), "=r"(r[3]) : "r"(addr));
}
__device__ __forceinline__ void mma16816h(float* d, const uint32_t* a, const uint32_t* b) {
    asm volatile(
        "mma.sync.aligned.m16n8k16.row.col.f32.f16.f16.f32 "
        "{%0,%1,%2,%3}, {%4,%5,%6,%7}, {%8,%9}, {%0,%1,%2,%3};"
        : "+f"(d[0]), "+f"(d[1]), "+f"(d[2]), "+f"(d[3])
        : "r"(a[0]), "r"(a[1]), "r"(a[2]), "r"(a[3]), "r"(b[0]), "r"(b[1]));
}

// ---------------- prep: detect, conv feat->fp16, zero deg, W fp16, bias ----
// 800k threads: thread i converts 8 floats of feat (6.4M total, exact fit).
__global__ void k_prep(const float* __restrict__ Wself, const float* __restrict__ bself,
                       const float* __restrict__ Wneigh, const float* __restrict__ bias,
                       const float* __restrict__ feat,
                       const unsigned* __restrict__ src_raw) {
    int i = blockIdx.x * blockDim.x + threadIdx.x;
    if (blockIdx.x == 0) {                       // int64-vs-int32 detection
        __shared__ unsigned sor[8];
        int t = threadIdx.x, lane = t & 31, w = t >> 5;
        unsigned v = src_raw[2 * t + 1];
        #pragma unroll
        for (int off = 16; off > 0; off >>= 1) v |= __shfl_xor_sync(0xffffffffu, v, off);
        if (lane == 0) sor[w] = v;
        __syncthreads();
        if (t == 0) {
            unsigned o = 0;
            #pragma unroll
            for (int j = 0; j < 8; j++) o |= sor[j];
            g_is64 = (o == 0) ? 1 : 0;
            g_rowoff[N_NODES] = N_EDGES;
            g_scan_ctr = 0;
        }
    }
    {   // feat -> fp16
        float4 a = __ldcs(&((const float4*)feat)[2 * i]);
        float4 b = __ldcs(&((const float4*)feat)[2 * i + 1]);
        __half2 h0 = __float22half2_rn(make_float2(a.x, a.y));
        __half2 h1 = __float22half2_rn(make_float2(a.z, a.w));
        __half2 h2 = __float22half2_rn(make_float2(b.x, b.y));
        __half2 h3 = __float22half2_rn(make_float2(b.z, b.w));
        uint4 o;
        o.x = *(uint32_t*)&h0; o.y = *(uint32_t*)&h1;
        o.z = *(uint32_t*)&h2; o.w = *(uint32_t*)&h3;
        ((uint4*)g_feat16)[i] = o;
    }
    if (i < N_NODES) g_deg[i] = 0;
    if (i < 128 * 256) {
        int n = i >> 8, k = i & 255;
        float w = (k < 128) ? Wself[n * 128 + k] : Wneigh[n * 128 + (k - 128)];
        __half h = __float2half_rn(w);
        g_Wh16[i] = *(unsigned short*)&h;
    }
    if (i < D) g_bcat[i] = bself[i] + bias[i];
}

// ---------------- CSR build ----------------
// hist: atomicAdd return value = this edge's rank within its dst bucket
__global__ void k_hist(const void* __restrict__ dst) {
    int e = blockIdx.x * blockDim.x + threadIdx.x;
    if (e < N_EDGES) {
        int d = edge_idx(dst, e, g_is64);
        unsigned short rk = (unsigned short)atomicAdd(&g_deg[d], 1);
        __stcs(&g_rank[e], rk);
    }
}

// block-level exclusive scan + last-block scans the 49 partials
__global__ void k_scan1() {
    __shared__ int wsum[32];
    __shared__ int s_last;
    int t = threadIdx.x, lane = t & 31, w = t >> 5;
    int i = blockIdx.x * SCAN_BLK + t;
    int v = (i < N_NODES) ? g_deg[i] : 0;
    int x = v;
    #pragma unroll
    for (int off = 1; off < 32; off <<= 1) {
        int y = __shfl_up_sync(0xffffffff, x, off);
        if (lane >= off) x += y;
    }
    if (lane == 31) wsum[w] = x;
    __syncthreads();
    if (w == 0) {
        int s = wsum[lane];
        #pragma unroll
        for (int off = 1; off < 32; off <<= 1) {
            int y = __shfl_up_sync(0xffffffff, s, off);
            if (lane >= off) s += y;
        }
        wsum[lane] = s;
    }
    __syncthreads();
    int pre = (w > 0) ? wsum[w - 1] : 0;
    if (i < N_NODES) g_rowoff[i] = x + pre - v;       // block-local exclusive
    if (t == SCAN_BLK - 1) g_bsum[blockIdx.x] = x + pre;
    if (t == 0) {
        __threadfence();
        s_last = (atomicAdd(&g_scan_ctr, 1) == NBLK - 1) ? 1 : 0;
    }
    __syncthreads();
    if (s_last) {
        __shared__ int ws2[2];
        if (t < 64) {
            int v2 = (t < NBLK) ? g_bsum[t] : 0;
            int x2 = v2;
            #pragma unroll
            for (int off = 1; off < 32; off <<= 1) {
                int y = __shfl_up_sync(0xffffffff, x2, off);
                if (lane >= off) x2 += y;
            }
            if (lane == 31) ws2[w] = x2;
            __syncthreads();
            if (w == 1) x2 += ws2[0];
            if (t < NBLK) g_bpre[t] = x2 - v2;
        } else {
            __syncthreads();
        }
        if (t == 0) g_scan_ctr = 0;                   // reset for next replay
    }
}

// scatter: atomic-free, rank precomputed in hist
__global__ void k_scatter(const void* __restrict__ src, const void* __restrict__ dst) {
    int e = blockIdx.x * blockDim.x + threadIdx.x;
    if (e < N_EDGES) {
        int is64 = g_is64;
        int d = edge_idx(dst, e, is64);
        int s = edge_idx(src, e, is64);
        int rk = (int)__ldcs(&g_rank[e]);
        __stcs(&g_edgesrc[g_rowoff[d] + g_bpre[d >> 10] + rk], (unsigned short)s);
    }
}

// ---------------- SpMM: warp per node, fp16 gather + fp32 mean -------------
__global__ void k_spmm() {
    int g = (blockIdx.x * blockDim.x + threadIdx.x) >> 5;
    int lane = threadIdx.x & 31;
    if (g >= N_NODES) return;
    int beg = g_rowoff[g] + g_bpre[g >> 10];
    int end = (g == N_NODES - 1) ? N_EDGES : g_rowoff[g + 1] + g_bpre[(g + 1) >> 10];
    float4 acc = make_float4(0.f, 0.f, 0.f, 0.f);
    int e = beg;
    for (; e + 7 < end; e += 8) {                    // 8 outstanding LDG.64/lane
        uint2 f[8];
        #pragma unroll
        for (int j = 0; j < 8; j++) {
            int s = (int)__ldcs(&g_edgesrc[e + j]);
            f[j] = *(const uint2*)(g_feat16 + (size_t)s * D + lane * 4);
        }
        #pragma unroll
        for (int j = 0; j < 8; j++) {
            float2 a = __half22float2(*(__half2*)&f[j].x);
            float2 b = __half22float2(*(__half2*)&f[j].y);
            acc.x += a.x; acc.y += a.y; acc.z += b.x; acc.w += b.y;
        }
    }
    for (; e < end; e++) {
        int s = (int)g_edgesrc[e];
        uint2 fv = *(const uint2*)(g_feat16 + (size_t)s * D + lane * 4);
        float2 a = __half22float2(*(__half2*)&fv.x);
        float2 b = __half22float2(*(__half2*)&fv.y);
        acc.x += a.x; acc.y += a.y; acc.z += b.x; acc.w += b.y;
    }
    float inv = (end > beg) ? 1.0f / (float)(end - beg) : 0.0f;
    acc.x *= inv; acc.y *= inv; acc.z *= inv; acc.w *= inv;
    *(float4*)(g_hneigh + (size_t)g * D + lane * 4) = acc;
}

// ---------------- HMMA fp16x2 GEMM: out = [feat|hneigh] @ W^T + bcat --------
// Block 256 thr / 8 warps, 3 CTAs/SM. Tile 128x128, K=256 in 4 phases of 64.
// A split hi+lo fp16 (~22-bit), B = fp16 hi only: D += Ahi*Bh + Alo*Bh.
// smem: Ahi/Alo/Bh @ 128 x 72 fp16 = 54KB.
#define AS 72
#define GSMEM (3 * 128 * AS * 2)
__global__ void __launch_bounds__(256, 3) k_gemm_mma(const float* __restrict__ feat,
                                                     float* __restrict__ out) {
    extern __shared__ unsigned short sm[];
    unsigned short* sAhi = sm;
    unsigned short* sAlo = sm + 128 * AS;
    unsigned short* sBh  = sm + 2 * 128 * AS;
    int tid = threadIdx.x, l = tid & 31, wid = tid >> 5;
    int wm = wid >> 1, wn = wid & 1;
    int row0 = blockIdx.x * MTILE;

    float acc[2][8][4] = {};

    uint32_t sbase = smem_u32(sm);
    uint32_t aRow = (uint32_t)(wm * 32 + (l & 7) + ((l >> 3) & 1) * 8);
    uint32_t aK   = (uint32_t)((l >> 4) * 8);
    uint32_t aHi  = sbase + (aRow * AS + aK) * 2;
    uint32_t aLo  = aHi + 128 * AS * 2;
    uint32_t bRow = (uint32_t)(wn * 64 + (l & 7) + (l >> 4) * 8);
    uint32_t bK   = (uint32_t)(((l >> 3) & 1) * 8);
    uint32_t bHi  = sbase + 2 * 128 * AS * 2 + (bRow * AS + bK) * 2;

    #pragma unroll 1
    for (int ph = 0; ph < 4; ph++) {
        int kb = ph * 64;
        const float* srcA = (ph < 2) ? (feat + ph * 64)
                                     : (g_hneigh + (ph - 2) * 64);
        // stage A: 128 rows x 64 k fp32 -> split into hi/lo fp16
        for (int i = tid; i < 2048; i += 256) {       // float4 units
            int r = i >> 4, c = i & 15;
            int grow = row0 + r;
            float4 f = make_float4(0.f, 0.f, 0.f, 0.f);
            if (grow < N_NODES)
                f = *(const float4*)(srcA + (size_t)grow * D + c * 4);
            ushort4 h, lo4;
            h_split(f.x, h.x, lo4.x); h_split(f.y, h.y, lo4.y);
            h_split(f.z, h.z, lo4.z); h_split(f.w, h.w, lo4.w);
            *(ushort4*)(sAhi + r * AS + c * 4) = h;
            *(ushort4*)(sAlo + r * AS + c * 4) = lo4;
        }
        // stage B: 128 rows x 64 k fp16
        for (int i = tid; i < 1024; i += 256) {       // uint4 units (8 fp16)
            int r = i >> 3, c = i & 7;
            *(uint4*)(sBh + r * AS + c * 8) =
                *(const uint4*)(g_Wh16 + (size_t)r * 256 + kb + c * 8);
        }
        __syncthreads();
        #pragma unroll
        for (int ks = 0; ks < 4; ks++) {
            uint32_t ah[2][4], al[2][4];
            ldsm4(ah[0], aHi + ks * 32);
            ldsm4(ah[1], aHi + ks * 32 + 16 * AS * 2);
            ldsm4(al[0], aLo + ks * 32);
            ldsm4(al[1], aLo + ks * 32 + 16 * AS * 2);
            #pragma unroll
            for (int np = 0; np < 4; np++) {
                uint32_t bh[4];
                ldsm4(bh, bHi + ks * 32 + np * 16 * AS * 2);
                #pragma unroll
                for (int mt = 0; mt < 2; mt++) {
                    mma16816h(acc[mt][2 * np + 0], ah[mt], bh + 0);
                    mma16816h(acc[mt][2 * np + 0], al[mt], bh + 0);
                    mma16816h(acc[mt][2 * np + 1], ah[mt], bh + 2);
                    mma16816h(acc[mt][2 * np + 1], al[mt], bh + 2);
                }
            }
        }
        __syncthreads();
    }

    // epilogue: c-frag lane l -> rows l/4 (+8), cols 2*(l%4) (+1)
    #pragma unroll
    for (int mt = 0; mt < 2; mt++) {
        #pragma unroll
        for (int half = 0; half < 2; half++) {
            int row = row0 + wm * 32 + mt * 16 + (l >> 2) + half * 8;
            if (row >= N_NODES) continue;
            #pragma unroll
            for (int nt = 0; nt < 8; nt++) {
                int col = wn * 64 + nt * 8 + (l & 3) * 2;
                float2 b = *(const float2*)(g_bcat + col);
                float2 o;
                o.x = acc[mt][nt][2 * half + 0] + b.x;
                o.y = acc[mt][nt][2 * half + 1] + b.y;
                *(float2*)(out + (size_t)row * D + col) = o;
            }
        }
    }
}

// ---------------- launcher ----------------
extern "C" void kernel_launch(void* const* d_in, const int* in_sizes, int n_in,
                              void* d_out, int out_size) {
    const float* feat   = (const float*)d_in[0];
    const void*  src    = d_in[1];
    const void*  dst    = d_in[2];
    const float* Wself  = (const float*)d_in[3];
    const float* bself  = (const float*)d_in[4];
    const float* Wneigh = (const float*)d_in[5];
    const float* bias   = (const float*)d_in[6];
    float* out = (float*)d_out;

    cudaFuncSetAttribute(k_gemm_mma, cudaFuncAttributeMaxDynamicSharedMemorySize, GSMEM);

    k_prep<<<(N_NODES * 16 + 255) / 256, 256>>>(Wself, bself, Wneigh, bias, feat,
                                                (const unsigned*)src);
    k_hist<<<(N_EDGES + 255) / 256, 256>>>(dst);
    k_scan1<<<NBLK, SCAN_BLK>>>();
    k_scatter<<<(N_EDGES + 255) / 256, 256>>>(src, dst);
    k_spmm<<<(N_NODES * 32 + 255) / 256, 256>>>();
    k_gemm_mma<<<NTILES, 256, GSMEM>>>(feat, out);
}

// round 14
// speedup vs baseline: 1.0882x; 1.0280x over previous
#include <cuda_runtime.h>
#include <cuda_bf16.h>
#include <cuda_fp16.h>
#include <cstdint>

#define N_NODES 50000
#define N_EDGES 800000
#define D 128
#define SCAN_BLK 1024
#define NBLK ((N_NODES + SCAN_BLK - 1) / SCAN_BLK)   // 49
#define MTILE 128
#define NTILES ((N_NODES + MTILE - 1) / MTILE)       // 391

// ---------------- device scratch ----------------
__device__ int   g_deg[N_NODES];                     // zeroed by static init, then by k_scatter for next replay
__device__ int   g_rowoff[N_NODES + 1];
__device__ unsigned short g_rank[N_EDGES];           // edge rank within dst bucket
__device__ int   g_edgesrc[N_EDGES];
__device__ int   g_bsum[NBLK];
__device__ int   g_bpre[NBLK];
__device__ int   g_scan_ctr = 0;
__device__ float g_hneigh[(size_t)N_NODES * D];      // fp32 mean-aggregated feats
__device__ unsigned short g_feat16[(size_t)N_NODES * D];  // fp16 feat (gather side)
__device__ unsigned short g_Wh16[128 * 256];         // fp16 W: [n][k] k<128 Wself, else Wneigh
__device__ float g_bcat[D];
__device__ int   g_is64;

// ---------------- small helpers ----------------
__device__ __forceinline__ int edge_idx(const void* p, int i, int is64) {
    return is64 ? (int)((const long long*)p)[i] : ((const int*)p)[i];
}
__device__ __forceinline__ void h_split(float x, unsigned short& hi, unsigned short& lo) {
    __half h = __float2half_rn(x);
    hi = *(unsigned short*)&h;
    float r = x - __half2float(h);
    __half l = __float2half_rn(r);
    lo = *(unsigned short*)&l;
}
__device__ __forceinline__ uint32_t smem_u32(const void* p) {
    uint32_t a;
    asm("{ .reg .u64 t; cvta.to.shared.u64 t, %1; cvt.u32.u64 %0, t; }" : "=r"(a) : "l"(p));
    return a;
}
// block-local int64-vs-int32 detection: OR of odd 32-bit words over the first
// 512 words of src. int64 ids < 50000 -> all zero; int32 ids -> nonzero w.p. 1.
// Every block computes the same value (deterministic).
__device__ __forceinline__ int detect_is64_block(const unsigned* src_raw) {
    __shared__ unsigned sor[8];
    int t = threadIdx.x, lane = t & 31, w = t >> 5;
    unsigned v = src_raw[2 * (t & 255) + 1];
    #pragma unroll
    for (int off = 16; off > 0; off >>= 1) v |= __shfl_xor_sync(0xffffffffu, v, off);
    if (lane == 0) sor[w & 7] = v;
    __syncthreads();
    unsigned o = sor[0] | sor[1] | sor[2] | sor[3] | sor[4] | sor[5] | sor[6] | sor[7];
    __syncthreads();
    return (o == 0) ? 1 : 0;
}
// warp-level MMA primitives (sm_80 PTX — safe for the harness's sm_103 ptxas target)
__device__ __forceinline__ void ldsm4(uint32_t* r, uint32_t addr) {
    asm volatile("ldmatrix.sync.aligned.m8n8.x4.shared.b16 {%0,%1,%2,%3}, [%4];"
        : "=r"(r[0]), "=r"(r[1]), "=r"(r[2]), "=r"(r[3]) : "r"(addr));
}
__device__ __forceinline__ void mma16816h(float* d, const uint32_t* a, const uint32_t* b) {
    asm volatile(
        "mma.sync.aligned.m16n8k16.row.col.f32.f16.f16.f32 "
        "{%0,%1,%2,%3}, {%4,%5,%6,%7}, {%8,%9}, {%0,%1,%2,%3};"
        : "+f"(d[0]), "+f"(d[1]), "+f"(d[2]), "+f"(d[3])
        : "r"(a[0]), "r"(a[1]), "r"(a[2]), "r"(a[3]), "r"(b[0]), "r"(b[1]));
}

// ---------------- hist (+ detect, W conv, bcat) -----------------------------
// g_deg is zero on entry (static init on call 1; k_scatter re-zeroes per replay).
__global__ void k_hist(const void* __restrict__ dst,
                       const float* __restrict__ Wself, const float* __restrict__ bself,
                       const float* __restrict__ Wneigh, const float* __restrict__ bias,
                       const unsigned* __restrict__ src_raw) {
    int is64 = detect_is64_block(src_raw);
    int e = blockIdx.x * blockDim.x + threadIdx.x;
    if (e >= N_EDGES) return;
    if (e == 0) {
        g_is64 = is64;
        g_rowoff[N_NODES] = N_EDGES;
    }
    if (e < 128 * 256) {
        int n = e >> 8, k = e & 255;
        float w = (k < 128) ? Wself[n * 128 + k] : Wneigh[n * 128 + (k - 128)];
        __half h = __float2half_rn(w);
        g_Wh16[e] = *(unsigned short*)&h;
    }
    if (e < D) g_bcat[e] = bself[e] + bias[e];
    int d = edge_idx(dst, e, is64);
    unsigned short rk = (unsigned short)atomicAdd(&g_deg[d], 1);
    __stcs(&g_rank[e], rk);
}

// block-level exclusive scan + last-block scans the 49 partials
__global__ void k_scan1() {
    __shared__ int wsum[32];
    __shared__ int s_last;
    int t = threadIdx.x, lane = t & 31, w = t >> 5;
    int i = blockIdx.x * SCAN_BLK + t;
    int v = (i < N_NODES) ? g_deg[i] : 0;
    int x = v;
    #pragma unroll
    for (int off = 1; off < 32; off <<= 1) {
        int y = __shfl_up_sync(0xffffffff, x, off);
        if (lane >= off) x += y;
    }
    if (lane == 31) wsum[w] = x;
    __syncthreads();
    if (w == 0) {
        int s = wsum[lane];
        #pragma unroll
        for (int off = 1; off < 32; off <<= 1) {
            int y = __shfl_up_sync(0xffffffff, s, off);
            if (lane >= off) s += y;
        }
        wsum[lane] = s;
    }
    __syncthreads();
    int pre = (w > 0) ? wsum[w - 1] : 0;
    if (i < N_NODES) g_rowoff[i] = x + pre - v;       // block-local exclusive
    if (t == SCAN_BLK - 1) g_bsum[blockIdx.x] = x + pre;
    if (t == 0) {
        __threadfence();
        s_last = (atomicAdd(&g_scan_ctr, 1) == NBLK - 1) ? 1 : 0;
    }
    __syncthreads();
    if (s_last) {
        __shared__ int ws2[2];
        if (t < 64) {
            int v2 = (t < NBLK) ? g_bsum[t] : 0;
            int x2 = v2;
            #pragma unroll
            for (int off = 1; off < 32; off <<= 1) {
                int y = __shfl_up_sync(0xffffffff, x2, off);
                if (lane >= off) x2 += y;
            }
            if (lane == 31) ws2[w] = x2;
            __syncthreads();
            if (w == 1) x2 += ws2[0];
            if (t < NBLK) g_bpre[t] = x2 - v2;
        } else {
            __syncthreads();
        }
        if (t == 0) g_scan_ctr = 0;                   // reset for next replay
    }
}

// ---------------- scatter (+ feat->fp16 conv, deg re-zero) -----------------
// Random-store latency of the scatter hides the streaming conversion.
__global__ void k_scatter(const void* __restrict__ src, const void* __restrict__ dst,
                          const float* __restrict__ feat) {
    int e = blockIdx.x * blockDim.x + threadIdx.x;
    if (e >= N_EDGES) return;
    {   // feat -> fp16: thread e converts 8 floats (800k x 8 = 6.4M, exact fit)
        float4 a = __ldcs(&((const float4*)feat)[2 * e]);
        float4 b = __ldcs(&((const float4*)feat)[2 * e + 1]);
        __half2 h0 = __float22half2_rn(make_float2(a.x, a.y));
        __half2 h1 = __float22half2_rn(make_float2(a.z, a.w));
        __half2 h2 = __float22half2_rn(make_float2(b.x, b.y));
        __half2 h3 = __float22half2_rn(make_float2(b.z, b.w));
        uint4 o;
        o.x = *(uint32_t*)&h0; o.y = *(uint32_t*)&h1;
        o.z = *(uint32_t*)&h2; o.w = *(uint32_t*)&h3;
        ((uint4*)g_feat16)[e] = o;
    }
    int is64 = g_is64;
    int d = edge_idx(dst, e, is64);
    int s = edge_idx(src, e, is64);
    int rk = (int)__ldcs(&g_rank[e]);
    __stcs(&g_edgesrc[g_rowoff[d] + g_bpre[d >> 10] + rk], s);
    if (e < N_NODES) g_deg[e] = 0;                   // re-zero for next replay
}

// ---------------- SpMM: warp per node, fp16 gather + fp32 mean -------------
__global__ void k_spmm() {
    int g = (blockIdx.x * blockDim.x + threadIdx.x) >> 5;
    int lane = threadIdx.x & 31;
    if (g >= N_NODES) return;
    int beg = g_rowoff[g] + g_bpre[g >> 10];
    int end = (g == N_NODES - 1) ? N_EDGES : g_rowoff[g + 1] + g_bpre[(g + 1) >> 10];
    float4 acc = make_float4(0.f, 0.f, 0.f, 0.f);
    int e = beg;
    for (; e + 7 < end; e += 8) {                    // 8 outstanding LDG.64/lane
        uint2 f[8];
        #pragma unroll
        for (int j = 0; j < 8; j++) {
            int s = __ldcs(&g_edgesrc[e + j]);
            f[j] = *(const uint2*)(g_feat16 + (size_t)s * D + lane * 4);
        }
        #pragma unroll
        for (int j = 0; j < 8; j++) {
            float2 a = __half22float2(*(__half2*)&f[j].x);
            float2 b = __half22float2(*(__half2*)&f[j].y);
            acc.x += a.x; acc.y += a.y; acc.z += b.x; acc.w += b.y;
        }
    }
    for (; e < end; e++) {
        int s = __ldcs(&g_edgesrc[e]);
        uint2 fv = *(const uint2*)(g_feat16 + (size_t)s * D + lane * 4);
        float2 a = __half22float2(*(__half2*)&fv.x);
        float2 b = __half22float2(*(__half2*)&fv.y);
        acc.x += a.x; acc.y += a.y; acc.z += b.x; acc.w += b.y;
    }
    float inv = (end > beg) ? 1.0f / (float)(end - beg) : 0.0f;
    acc.x *= inv; acc.y *= inv; acc.z *= inv; acc.w *= inv;
    *(float4*)(g_hneigh + (size_t)g * D + lane * 4) = acc;
}

// ---------------- HMMA fp16x2 GEMM: out = [feat|hneigh] @ W^T + bcat --------
// Block 256 thr / 8 warps, 3 CTAs/SM. Tile 128x128, K=256 in 4 phases of 64.
// A split hi+lo fp16 (~22-bit), B = fp16 hi only: D += Ahi*Bh + Alo*Bh.
// smem: Ahi/Alo/Bh @ 128 x 72 fp16 = 54KB.
#define AS 72
#define GSMEM (3 * 128 * AS * 2)
__global__ void __launch_bounds__(256, 3) k_gemm_mma(const float* __restrict__ feat,
                                                     float* __restrict__ out) {
    extern __shared__ unsigned short sm[];
    unsigned short* sAhi = sm;
    unsigned short* sAlo = sm + 128 * AS;
    unsigned short* sBh  = sm + 2 * 128 * AS;
    int tid = threadIdx.x, l = tid & 31, wid = tid >> 5;
    int wm = wid >> 1, wn = wid & 1;
    int row0 = blockIdx.x * MTILE;

    float acc[2][8][4] = {};

    uint32_t sbase = smem_u32(sm);
    uint32_t aRow = (uint32_t)(wm * 32 + (l & 7) + ((l >> 3) & 1) * 8);
    uint32_t aK   = (uint32_t)((l >> 4) * 8);
    uint32_t aHi  = sbase + (aRow * AS + aK) * 2;
    uint32_t aLo  = aHi + 128 * AS * 2;
    uint32_t bRow = (uint32_t)(wn * 64 + (l & 7) + (l >> 4) * 8);
    uint32_t bK   = (uint32_t)(((l >> 3) & 1) * 8);
    uint32_t bHi  = sbase + 2 * 128 * AS * 2 + (bRow * AS + bK) * 2;

    #pragma unroll 1
    for (int ph = 0; ph < 4; ph++) {
        int kb = ph * 64;
        const float* srcA = (ph < 2) ? (feat + ph * 64)
                                     : (g_hneigh + (ph - 2) * 64);
        // stage A: 128 rows x 64 k fp32 -> split into hi/lo fp16
        for (int i = tid; i < 2048; i += 256) {       // float4 units
            int r = i >> 4, c = i & 15;
            int grow = row0 + r;
            float4 f = make_float4(0.f, 0.f, 0.f, 0.f);
            if (grow < N_NODES)
                f = *(const float4*)(srcA + (size_t)grow * D + c * 4);
            ushort4 h, lo4;
            h_split(f.x, h.x, lo4.x); h_split(f.y, h.y, lo4.y);
            h_split(f.z, h.z, lo4.z); h_split(f.w, h.w, lo4.w);
            *(ushort4*)(sAhi + r * AS + c * 4) = h;
            *(ushort4*)(sAlo + r * AS + c * 4) = lo4;
        }
        // stage B: 128 rows x 64 k fp16
        for (int i = tid; i < 1024; i += 256) {       // uint4 units (8 fp16)
            int r = i >> 3, c = i & 7;
            *(uint4*)(sBh + r * AS + c * 8) =
                *(const uint4*)(g_Wh16 + (size_t)r * 256 + kb + c * 8);
        }
        __syncthreads();
        #pragma unroll
        for (int ks = 0; ks < 4; ks++) {
            uint32_t ah[2][4], al[2][4];
            ldsm4(ah[0], aHi + ks * 32);
            ldsm4(ah[1], aHi + ks * 32 + 16 * AS * 2);
            ldsm4(al[0], aLo + ks * 32);
            ldsm4(al[1], aLo + ks * 32 + 16 * AS * 2);
            #pragma unroll
            for (int np = 0; np < 4; np++) {
                uint32_t bh[4];
                ldsm4(bh, bHi + ks * 32 + np * 16 * AS * 2);
                #pragma unroll
                for (int mt = 0; mt < 2; mt++) {
                    mma16816h(acc[mt][2 * np + 0], ah[mt], bh + 0);
                    mma16816h(acc[mt][2 * np + 0], al[mt], bh + 0);
                    mma16816h(acc[mt][2 * np + 1], ah[mt], bh + 2);
                    mma16816h(acc[mt][2 * np + 1], al[mt], bh + 2);
                }
            }
        }
        __syncthreads();
    }

    // epilogue: c-frag lane l -> rows l/4 (+8), cols 2*(l%4) (+1)
    #pragma unroll
    for (int mt = 0; mt < 2; mt++) {
        #pragma unroll
        for (int half = 0; half < 2; half++) {
            int row = row0 + wm * 32 + mt * 16 + (l >> 2) + half * 8;
            if (row >= N_NODES) continue;
            #pragma unroll
            for (int nt = 0; nt < 8; nt++) {
                int col = wn * 64 + nt * 8 + (l & 3) * 2;
                float2 b = *(const float2*)(g_bcat + col);
                float2 o;
                o.x = acc[mt][nt][2 * half + 0] + b.x;
                o.y = acc[mt][nt][2 * half + 1] + b.y;
                *(float2*)(out + (size_t)row * D + col) = o;
            }
        }
    }
}

// ---------------- launcher ----------------
extern "C" void kernel_launch(void* const* d_in, const int* in_sizes, int n_in,
                              void* d_out, int out_size) {
    const float* feat   = (const float*)d_in[0];
    const void*  src    = d_in[1];
    const void*  dst    = d_in[2];
    const float* Wself  = (const float*)d_in[3];
    const float* bself  = (const float*)d_in[4];
    const float* Wneigh = (const float*)d_in[5];
    const float* bias   = (const float*)d_in[6];
    float* out = (float*)d_out;

    cudaFuncSetAttribute(k_gemm_mma, cudaFuncAttributeMaxDynamicSharedMemorySize, GSMEM);

    k_hist<<<(N_EDGES + 255) / 256, 256>>>(dst, Wself, bself, Wneigh, bias,
                                           (const unsigned*)src);
    k_scan1<<<NBLK, SCAN_BLK>>>();
    k_scatter<<<(N_EDGES + 255) / 256, 256>>>(src, dst, feat);
    k_spmm<<<(N_NODES * 32 + 255) / 256, 256>>>();
    k_gemm_mma<<<NTILES, 256, GSMEM>>>(feat, out);
}

// round 16
// speedup vs baseline: 1.3076x; 1.2016x over previous
#include <cuda_runtime.h>
#include <cuda_bf16.h>
#include <cuda_fp16.h>
#include <cstdint>

#define N_NODES 50000
#define N_PAD 50176                                  // padded rows (tile-safe cp.async reads)
#define N_EDGES 800000
#define D 128
#define SCAN_BLK 1024
#define NBLK ((N_NODES + SCAN_BLK - 1) / SCAN_BLK)   // 49
#define MTILE 128
#define NTILES ((N_NODES + MTILE - 1) / MTILE)       // 391

// ---------------- device scratch ----------------
__device__ int   g_deg[N_NODES];                     // zero at start; k_scatter re-zeroes per replay
__device__ int   g_rowoff[N_NODES + 1];
__device__ unsigned short g_rank[N_EDGES];
__device__ int   g_edgesrc[N_EDGES];
__device__ int   g_bsum[NBLK];
__device__ int   g_bpre[NBLK];
__device__ int   g_scan_ctr = 0;
__device__ unsigned short g_Xhi[(size_t)N_PAD * 256];  // fp16 hi: [row][k] k<128 feat, k>=128 hneigh
__device__ unsigned short g_Xlo[(size_t)N_PAD * 256];  // fp16 lo residual
__device__ unsigned short g_Wh16[128 * 256];         // fp16 W: [n][k] k<128 Wself, else Wneigh
__device__ float g_bcat[D];
__device__ int   g_is64;

// ---------------- small helpers ----------------
__device__ __forceinline__ int edge_idx(const void* p, int i, int is64) {
    return is64 ? (int)((const long long*)p)[i] : ((const int*)p)[i];
}
__device__ __forceinline__ void h_split(float x, unsigned short& hi, unsigned short& lo) {
    __half h = __float2half_rn(x);
    hi = *(unsigned short*)&h;
    float r = x - __half2float(h);
    __half l = __float2half_rn(r);
    lo = *(unsigned short*)&l;
}
__device__ __forceinline__ uint32_t smem_u32(const void* p) {
    uint32_t a;
    asm("{ .reg .u64 t; cvta.to.shared.u64 t, %1; cvt.u32.u64 %0, t; }" : "=r"(a) : "l"(p));
    return a;
}
__device__ __forceinline__ int detect_is64_block(const unsigned* src_raw) {
    __shared__ unsigned sor[8];
    int t = threadIdx.x, lane = t & 31, w = t >> 5;
    unsigned v = src_raw[2 * (t & 255) + 1];
    #pragma unroll
    for (int off = 16; off > 0; off >>= 1) v |= __shfl_xor_sync(0xffffffffu, v, off);
    if (lane == 0) sor[w & 7] = v;
    __syncthreads();
    unsigned o = sor[0] | sor[1] | sor[2] | sor[3] | sor[4] | sor[5] | sor[6] | sor[7];
    __syncthreads();
    return (o == 0) ? 1 : 0;
}
// warp-level MMA primitives (sm_80 PTX — safe for the harness's sm_103 ptxas target)
__device__ __forceinline__ void ldsm4(uint32_t* r, uint32_t addr) {
    asm volatile("ldmatrix.sync.aligned.m8n8.x4.shared.b16 {%0,%1,%2,%3}, [%4];"
        : "=r"(r[0]), "=r"(r[1]), "=r"(r[2]), "=r"(r[3]) : "r"(addr));
}
__device__ __forceinline__ void mma16816h(float* d, const uint32_t* a, const uint32_t* b) {
    asm volatile(
        "mma.sync.aligned.m16n8k16.row.col.f32.f16.f16.f32 "
        "{%0,%1,%2,%3}, {%4,%5,%6,%7}, {%8,%9}, {%0,%1,%2,%3};"
        : "+f"(d[0]), "+f"(d[1]), "+f"(d[2]), "+f"(d[3])
        : "r"(a[0]), "r"(a[1]), "r"(a[2]), "r"(a[3]), "r"(b[0]), "r"(b[1]));
}
// cp.async (sm_80 PTX)
#define CP_ASYNC16(saddr, gptr) \
    asm volatile("cp.async.cg.shared.global [%0], [%1], 16;" :: "r"(saddr), "l"(gptr) : "memory")
#define CP_COMMIT() asm volatile("cp.async.commit_group;" ::: "memory")
#define CP_WAIT0()  asm volatile("cp.async.wait_group 0;" ::: "memory")

// ---------------- hist (+ detect, W conv, bcat) -----------------------------
__global__ void k_hist(const void* __restrict__ dst,
                       const float* __restrict__ Wself, const float* __restrict__ bself,
                       const float* __restrict__ Wneigh, const float* __restrict__ bias,
                       const unsigned* __restrict__ src_raw) {
    int is64 = detect_is64_block(src_raw);
    int e = blockIdx.x * blockDim.x + threadIdx.x;
    if (e >= N_EDGES) return;
    if (e == 0) {
        g_is64 = is64;
        g_rowoff[N_NODES] = N_EDGES;
    }
    if (e < 128 * 256) {
        int n = e >> 8, k = e & 255;
        float w = (k < 128) ? Wself[n * 128 + k] : Wneigh[n * 128 + (k - 128)];
        __half h = __float2half_rn(w);
        g_Wh16[e] = *(unsigned short*)&h;
    }
    if (e < D) g_bcat[e] = bself[e] + bias[e];
    int d = edge_idx(dst, e, is64);
    unsigned short rk = (unsigned short)atomicAdd(&g_deg[d], 1);
    __stcs(&g_rank[e], rk);
}

// block-level exclusive scan + last-block scans the 49 partials
__global__ void k_scan1() {
    __shared__ int wsum[32];
    __shared__ int s_last;
    int t = threadIdx.x, lane = t & 31, w = t >> 5;
    int i = blockIdx.x * SCAN_BLK + t;
    int v = (i < N_NODES) ? g_deg[i] : 0;
    int x = v;
    #pragma unroll
    for (int off = 1; off < 32; off <<= 1) {
        int y = __shfl_up_sync(0xffffffff, x, off);
        if (lane >= off) x += y;
    }
    if (lane == 31) wsum[w] = x;
    __syncthreads();
    if (w == 0) {
        int s = wsum[lane];
        #pragma unroll
        for (int off = 1; off < 32; off <<= 1) {
            int y = __shfl_up_sync(0xffffffff, s, off);
            if (lane >= off) s += y;
        }
        wsum[lane] = s;
    }
    __syncthreads();
    int pre = (w > 0) ? wsum[w - 1] : 0;
    if (i < N_NODES) g_rowoff[i] = x + pre - v;
    if (t == SCAN_BLK - 1) g_bsum[blockIdx.x] = x + pre;
    if (t == 0) {
        __threadfence();
        s_last = (atomicAdd(&g_scan_ctr, 1) == NBLK - 1) ? 1 : 0;
    }
    __syncthreads();
    if (s_last) {
        __shared__ int ws2[2];
        if (t < 64) {
            int v2 = (t < NBLK) ? g_bsum[t] : 0;
            int x2 = v2;
            #pragma unroll
            for (int off = 1; off < 32; off <<= 1) {
                int y = __shfl_up_sync(0xffffffff, x2, off);
                if (lane >= off) x2 += y;
            }
            if (lane == 31) ws2[w] = x2;
            __syncthreads();
            if (w == 1) x2 += ws2[0];
            if (t < NBLK) g_bpre[t] = x2 - v2;
        } else {
            __syncthreads();
        }
        if (t == 0) g_scan_ctr = 0;
    }
}

// ---------------- scatter (+ feat hi/lo split, deg re-zero) ----------------
__global__ void k_scatter(const void* __restrict__ src, const void* __restrict__ dst,
                          const float* __restrict__ feat) {
    int e = blockIdx.x * blockDim.x + threadIdx.x;
    if (e >= N_EDGES) return;
    {   // feat -> hi/lo fp16: thread e covers 8 floats; row = e/16, col = (e%16)*8
        float4 a = __ldcs(&((const float4*)feat)[2 * e]);
        float4 b = __ldcs(&((const float4*)feat)[2 * e + 1]);
        unsigned short h[8], l[8];
        h_split(a.x, h[0], l[0]); h_split(a.y, h[1], l[1]);
        h_split(a.z, h[2], l[2]); h_split(a.w, h[3], l[3]);
        h_split(b.x, h[4], l[4]); h_split(b.y, h[5], l[5]);
        h_split(b.z, h[6], l[6]); h_split(b.w, h[7], l[7]);
        size_t o = (size_t)(e >> 4) * 256 + (e & 15) * 8;
        *(uint4*)(g_Xhi + o) = *(uint4*)h;
        *(uint4*)(g_Xlo + o) = *(uint4*)l;
    }
    int is64 = g_is64;
    int d = edge_idx(dst, e, is64);
    int s = edge_idx(src, e, is64);
    int rk = (int)__ldcs(&g_rank[e]);
    __stcs(&g_edgesrc[g_rowoff[d] + g_bpre[d >> 10] + rk], s);
    if (e < N_NODES) g_deg[e] = 0;                   // re-zero for next replay
}

// ---------------- SpMM: warp per node, fp16 gather + fp32 tree mean --------
__device__ __forceinline__ float4 h2f4(uint2 v) {
    float2 a = __half22float2(*(__half2*)&v.x);
    float2 b = __half22float2(*(__half2*)&v.y);
    return make_float4(a.x, a.y, b.x, b.y);
}
__device__ __forceinline__ float4 add4(float4 a, float4 b) {
    return make_float4(a.x + b.x, a.y + b.y, a.z + b.z, a.w + b.w);
}
__global__ void k_spmm() {
    int g = (blockIdx.x * blockDim.x + threadIdx.x) >> 5;
    int lane = threadIdx.x & 31;
    if (g >= N_NODES) return;
    int beg = g_rowoff[g] + g_bpre[g >> 10];
    int end = (g == N_NODES - 1) ? N_EDGES : g_rowoff[g + 1] + g_bpre[(g + 1) >> 10];
    float4 acc = make_float4(0.f, 0.f, 0.f, 0.f);
    int e = beg;
    for (; e + 7 < end; e += 8) {                    // 8 outstanding LDG.64/lane
        uint2 f[8];
        #pragma unroll
        for (int j = 0; j < 8; j++) {
            int s = __ldcs(&g_edgesrc[e + j]);
            f[j] = *(const uint2*)(g_Xhi + (size_t)s * 256 + lane * 4);
        }
        float4 t0 = add4(h2f4(f[0]), h2f4(f[1]));
        float4 t1 = add4(h2f4(f[2]), h2f4(f[3]));
        float4 t2 = add4(h2f4(f[4]), h2f4(f[5]));
        float4 t3 = add4(h2f4(f[6]), h2f4(f[7]));
        acc = add4(acc, add4(add4(t0, t1), add4(t2, t3)));
    }
    for (; e < end; e++) {
        int s = __ldcs(&g_edgesrc[e]);
        acc = add4(acc, h2f4(*(const uint2*)(g_Xhi + (size_t)s * 256 + lane * 4)));
    }
    float inv = (end > beg) ? 1.0f / (float)(end - beg) : 0.0f;
    acc.x *= inv; acc.y *= inv; acc.z *= inv; acc.w *= inv;
    unsigned short h[4], l[4];
    h_split(acc.x, h[0], l[0]); h_split(acc.y, h[1], l[1]);
    h_split(acc.z, h[2], l[2]); h_split(acc.w, h[3], l[3]);
    size_t o = (size_t)g * 256 + 128 + lane * 4;
    *(ushort4*)(g_Xhi + o) = *(ushort4*)h;
    *(ushort4*)(g_Xlo + o) = *(ushort4*)l;
}

// ---------------- HMMA fp16x2 GEMM, cp.async double-buffered ----------------
// Tile 128x128, K=256 in 4 phases of 64. A = Xhi+Xlo (pure copy), B = Wh16.
// smem: 2 buffers x (Ahi/Alo/Bh @ 128 x 72 fp16) = 108KB, 2 CTAs/SM.
// D += Ahi*Bh + Alo*Bh (fp32 accum).
#define AS 72
#define BUFHALF (3 * 128 * AS)
#define GSMEM (2 * BUFHALF * 2)
__device__ __forceinline__ void stage_phase(uint32_t sbase, int buf, int ph, int row0) {
    int tid = threadIdx.x;
    int kb = ph * 64;
    uint32_t b0 = sbase + (uint32_t)buf * BUFHALF * 2;
    #pragma unroll
    for (int i = tid; i < 1024; i += 256) {          // A hi: 16B chunks
        int r = i >> 3, c = i & 7;
        uint32_t sa = b0 + (uint32_t)(r * AS + c * 8) * 2;
        CP_ASYNC16(sa, g_Xhi + (size_t)(row0 + r) * 256 + kb + c * 8);
    }
    #pragma unroll
    for (int i = tid; i < 1024; i += 256) {          // A lo
        int r = i >> 3, c = i & 7;
        uint32_t sa = b0 + (uint32_t)(128 * AS + r * AS + c * 8) * 2;
        CP_ASYNC16(sa, g_Xlo + (size_t)(row0 + r) * 256 + kb + c * 8);
    }
    #pragma unroll
    for (int i = tid; i < 1024; i += 256) {          // B
        int r = i >> 3, c = i & 7;
        uint32_t sa = b0 + (uint32_t)(2 * 128 * AS + r * AS + c * 8) * 2;
        CP_ASYNC16(sa, g_Wh16 + (size_t)r * 256 + kb + c * 8);
    }
}
__global__ void __launch_bounds__(256, 2) k_gemm_mma(float* __restrict__ out) {
    extern __shared__ unsigned short sm[];
    int tid = threadIdx.x, l = tid & 31, wid = tid >> 5;
    int wm = wid >> 1, wn = wid & 1;
    int row0 = blockIdx.x * MTILE;

    float acc[2][8][4] = {};

    uint32_t sbase = smem_u32(sm);
    uint32_t aRow = (uint32_t)(wm * 32 + (l & 7) + ((l >> 3) & 1) * 8);
    uint32_t aK   = (uint32_t)((l >> 4) * 8);
    uint32_t aHiO = (aRow * AS + aK) * 2;
    uint32_t aLoO = aHiO + 128 * AS * 2;
    uint32_t bRow = (uint32_t)(wn * 64 + (l & 7) + (l >> 4) * 8);
    uint32_t bK   = (uint32_t)(((l >> 3) & 1) * 8);
    uint32_t bHiO = 2 * 128 * AS * 2 + (bRow * AS + bK) * 2;

    stage_phase(sbase, 0, 0, row0);
    CP_COMMIT();

    #pragma unroll 1
    for (int ph = 0; ph < 4; ph++) {
        CP_WAIT0();
        __syncthreads();
        if (ph < 3) {
            stage_phase(sbase, (ph + 1) & 1, ph + 1, row0);
            CP_COMMIT();
        }
        uint32_t b0 = sbase + (uint32_t)(ph & 1) * BUFHALF * 2;
        uint32_t aHi = b0 + aHiO, aLo = b0 + aLoO, bHi = b0 + bHiO;
        #pragma unroll
        for (int ks = 0; ks < 4; ks++) {
            uint32_t ah[2][4], al[2][4];
            ldsm4(ah[0], aHi + ks * 32);
            ldsm4(ah[1], aHi + ks * 32 + 16 * AS * 2);
            ldsm4(al[0], aLo + ks * 32);
            ldsm4(al[1], aLo + ks * 32 + 16 * AS * 2);
            #pragma unroll
            for (int np = 0; np < 4; np++) {
                uint32_t bh[4];
                ldsm4(bh, bHi + ks * 32 + np * 16 * AS * 2);
                #pragma unroll
                for (int mt = 0; mt < 2; mt++) {
                    mma16816h(acc[mt][2 * np + 0], ah[mt], bh + 0);
                    mma16816h(acc[mt][2 * np + 0], al[mt], bh + 0);
                    mma16816h(acc[mt][2 * np + 1], ah[mt], bh + 2);
                    mma16816h(acc[mt][2 * np + 1], al[mt], bh + 2);
                }
            }
        }
        __syncthreads();   // all warps done reading buf before it is restaged
    }

    // epilogue: c-frag lane l -> rows l/4 (+8), cols 2*(l%4) (+1)
    #pragma unroll
    for (int mt = 0; mt < 2; mt++) {
        #pragma unroll
        for (int half = 0; half < 2; half++) {
            int row = row0 + wm * 32 + mt * 16 + (l >> 2) + half * 8;
            if (row >= N_NODES) continue;
            #pragma unroll
            for (int nt = 0; nt < 8; nt++) {
                int col = wn * 64 + nt * 8 + (l & 3) * 2;
                float2 b = *(const float2*)(g_bcat + col);
                float2 o;
                o.x = acc[mt][nt][2 * half + 0] + b.x;
                o.y = acc[mt][nt][2 * half + 1] + b.y;
                *(float2*)(out + (size_t)row * D + col) = o;
            }
        }
    }
}

// ---------------- launcher ----------------
extern "C" void kernel_launch(void* const* d_in, const int* in_sizes, int n_in,
                              void* d_out, int out_size) {
    const float* feat   = (const float*)d_in[0];
    const void*  src    = d_in[1];
    const void*  dst    = d_in[2];
    const float* Wself  = (const float*)d_in[3];
    const float* bself  = (const float*)d_in[4];
    const float* Wneigh = (const float*)d_in[5];
    const float* bias   = (const float*)d_in[6];
    float* out = (float*)d_out;

    cudaFuncSetAttribute(k_gemm_mma, cudaFuncAttributeMaxDynamicSharedMemorySize, GSMEM);

    k_hist<<<(N_EDGES + 255) / 256, 256>>>(dst, Wself, bself, Wneigh, bias,
                                           (const unsigned*)src);
    k_scan1<<<NBLK, SCAN_BLK>>>();
    k_scatter<<<(N_EDGES + 255) / 256, 256>>>(src, dst, feat);
    k_spmm<<<(N_NODES * 32 + 255) / 256, 256>>>();
    k_gemm_mma<<<NTILES, 256, GSMEM>>>(out);
}